// round 6
// baseline (speedup 1.0000x reference)
#include <cuda_runtime.h>

#define Bx 4
#define Lx 512
#define Dx 128
#define LOG2E 1.4426950408889634f

// Scratch (static device arrays: allowed; no allocations anywhere)
// g_QA[row][d] = (a, w'*a) with a = tanh(q), w' = w*log2e.  g_KB likewise for k.
__device__ float2 g_QA[Bx * Lx * Dx];
__device__ float2 g_KB[Bx * Lx * Dx];
__device__ float g_S[(size_t)Bx * Lx * Lx];

__device__ __forceinline__ float tanh_fast(float v) {
    float y;
    asm("tanh.approx.f32 %0, %1;" : "=f"(y) : "f"(v));
    return y;
}
__device__ __forceinline__ float rcp_fast(float v) {
    float y;
    asm("rcp.approx.f32 %0, %1;" : "=f"(y) : "f"(v));
    return y;
}

// ---------------------------------------------------------------------------
// Kernel 1: tiled GEMM  proj = x @ W^T + b, epilogue a=tanh(proj), wa=w'*a.
// blockIdx.y: 0 -> (Wq,bq)->g_QA, 1 -> (Wk,bk)->g_KB.
// Block: 16 rows x 128 cols, 256 threads, thread tile 4 rows x 2 cols.
// W staged in smem transposed [d][e] in 32-d chunks; x staged [d][r].
// ---------------------------------------------------------------------------
__global__ __launch_bounds__(256) void qk_kernel(
        const float* __restrict__ x,
        const float* __restrict__ Wq, const float* __restrict__ bq,
        const float* __restrict__ Wk, const float* __restrict__ bk,
        const float* __restrict__ w) {
    __shared__ float Wsh[32][130];   // [d][e], stride even for LDS.64
    __shared__ float xsh[32][20];    // [d][r], stride mult-of-4 for LDS.128

    int which = blockIdx.y;
    int row0 = blockIdx.x * 16;      // global row in [0, B*L)
    const float* W = which ? Wk : Wq;
    const float* bias = which ? bk : bq;
    float2* outp = which ? g_KB : g_QA;

    int tid = threadIdx.x;
    int eidx = tid & 63;             // e pair: e0 = 2*eidx
    int e0 = 2 * eidx;
    int rg = tid >> 6;               // row group: rows 4*rg .. 4*rg+3

    const float4* W4 = (const float4*)W;     // [128][32] float4 per row
    const float4* x4 = (const float4*)(x + (size_t)row0 * Dx);

    float acc[4][2];
#pragma unroll
    for (int r = 0; r < 4; r++) { acc[r][0] = 0.f; acc[r][1] = 0.f; }

    for (int c = 0; c < 4; c++) {            // d chunks of 32
        int dc4 = c * 8;                     // float4 offset within row
        __syncthreads();
        // Stage W chunk: 128 e x 32 d -> transposed. 4 float4 per thread.
#pragma unroll
        for (int k = 0; k < 4; k++) {
            int idx = tid + 256 * k;         // 0..1023
            int e = idx >> 3, j4 = idx & 7;
            float4 v = W4[(size_t)e * 32 + dc4 + j4];
            Wsh[4 * j4 + 0][e] = v.x;
            Wsh[4 * j4 + 1][e] = v.y;
            Wsh[4 * j4 + 2][e] = v.z;
            Wsh[4 * j4 + 3][e] = v.w;
        }
        // Stage x chunk: 16 r x 32 d -> transposed. threads < 128.
        if (tid < 128) {
            int r = tid >> 3, j4 = tid & 7;
            float4 v = x4[(size_t)r * 32 + dc4 + j4];
            xsh[4 * j4 + 0][r] = v.x;
            xsh[4 * j4 + 1][r] = v.y;
            xsh[4 * j4 + 2][r] = v.z;
            xsh[4 * j4 + 3][r] = v.w;
        }
        __syncthreads();

#pragma unroll
        for (int d = 0; d < 32; d++) {
            float2 wv = *(const float2*)&Wsh[d][e0];
            float4 xv = *(const float4*)&xsh[d][4 * rg];
            acc[0][0] += wv.x * xv.x;  acc[0][1] += wv.y * xv.x;
            acc[1][0] += wv.x * xv.y;  acc[1][1] += wv.y * xv.y;
            acc[2][0] += wv.x * xv.z;  acc[2][1] += wv.y * xv.z;
            acc[3][0] += wv.x * xv.w;  acc[3][1] += wv.y * xv.w;
        }
    }

    float b0 = bias[e0], b1 = bias[e0 + 1];
    float wl0 = w[e0] * LOG2E, wl1 = w[e0 + 1] * LOG2E;
#pragma unroll
    for (int r = 0; r < 4; r++) {
        int row = row0 + 4 * rg + r;
        float a0 = tanh_fast(acc[r][0] + b0);
        float a1 = tanh_fast(acc[r][1] + b1);
        outp[(size_t)row * Dx + e0]     = make_float2(a0, wl0 * a0);
        outp[(size_t)row * Dx + e0 + 1] = make_float2(a1, wl1 * a1);
    }
}

// ---------------------------------------------------------------------------
// Kernel 2: S[b,i,j] = sum_d (wa[i,d]+wb[j,d]) * rcp(1 + a[i,d]*b[j,d])
// (exact tanh addition formula; bw dropped — cancels in softmax; log2e
//  pre-folded into wa/wb so kernel 3 can exp2 directly.)
// Tile 16i x 32j, 256 threads (ty=i, tx -> j=tx,tx+16); d in 4 chunks of 32.
// MUFU.RCP-bound by design (~rt8, 2x cheaper than tanh's rt16).
// ---------------------------------------------------------------------------
__global__ __launch_bounds__(256) void score_kernel() {
    __shared__ float4 QAs[16][17];   // [i][dp] (a_d, wa_d, a_d+1, wa_d+1)
    __shared__ float4 KBs[32][17];   // [j][dp]

    int tid = threadIdx.x;
    int b = blockIdx.z;
    int i0 = blockIdx.y * 16;
    int j0 = blockIdx.x * 32;

    const float4* QA4 = (const float4*)g_QA + ((size_t)b * Lx + i0) * 64;  // 64 f4/row
    const float4* KB4 = (const float4*)g_KB + ((size_t)b * Lx + j0) * 64;

    int ty = tid >> 4;   // i row 0..15
    int tx = tid & 15;   // j cols tx, tx+16

    float acc0 = 0.f, acc1 = 0.f;

    for (int c = 0; c < 4; c++) {
        int dp0 = c * 16;
        __syncthreads();
        {   // stage QA: 16 rows x 16 f4 (1/thread), KB: 32 x 16 (2/thread)
            int r = tid >> 4, dd = tid & 15;
            QAs[r][dd] = QA4[(size_t)r * 64 + dp0 + dd];
            KBs[r][dd] = KB4[(size_t)r * 64 + dp0 + dd];
            KBs[r + 16][dd] = KB4[(size_t)(r + 16) * 64 + dp0 + dd];
        }
        __syncthreads();

#pragma unroll
        for (int dp = 0; dp < 16; dp++) {
            float4 qv = QAs[ty][dp];
            float4 k0 = KBs[tx][dp];
            float4 k1 = KBs[tx + 16][dp];

            float n, den;
            n = qv.y + k0.y;  den = fmaf(qv.x, k0.x, 1.0f);
            acc0 = fmaf(n, rcp_fast(den), acc0);
            n = qv.w + k0.w;  den = fmaf(qv.z, k0.z, 1.0f);
            acc0 = fmaf(n, rcp_fast(den), acc0);
            n = qv.y + k1.y;  den = fmaf(qv.x, k1.x, 1.0f);
            acc1 = fmaf(n, rcp_fast(den), acc1);
            n = qv.w + k1.w;  den = fmaf(qv.z, k1.z, 1.0f);
            acc1 = fmaf(n, rcp_fast(den), acc1);
        }
    }

    float* Sb = g_S + (((size_t)b * Lx + i0 + ty) * Lx + j0);
    Sb[tx] = acc0;
    Sb[tx + 16] = acc1;
}

// ---------------------------------------------------------------------------
// Kernel 3: softmax over j (scores pre-scaled by log2e -> exp2 direct)
// + out = attn @ x. 8 query rows per block (grid 256), 256 threads.
// ---------------------------------------------------------------------------
__global__ __launch_bounds__(256) void out_kernel(const float* __restrict__ x,
                                                  float* __restrict__ out) {
    __shared__ float Ps[8][Lx];    // 16 KB
    __shared__ float linv[8];

    int row0 = blockIdx.x * 8;         // global row in [0, B*L)
    int bb = row0 >> 9;                // / L

    const float4* S4 = (const float4*)(g_S + (size_t)row0 * Lx);
    for (int t = threadIdx.x; t < 8 * Lx / 4; t += 256)
        ((float4*)Ps)[t] = S4[t];
    __syncthreads();

    int warp = threadIdx.x >> 5;   // row 0..7
    int lane = threadIdx.x & 31;
    {
        int r = warp;
        float v[16];
        float m = -1e30f;
#pragma unroll
        for (int c = 0; c < 16; c++) {
            v[c] = Ps[r][lane + c * 32];
            m = fmaxf(m, v[c]);
        }
#pragma unroll
        for (int o = 16; o; o >>= 1) m = fmaxf(m, __shfl_xor_sync(0xffffffffu, m, o));
        float s = 0.f;
#pragma unroll
        for (int c = 0; c < 16; c++) {
            float e = exp2f(v[c] - m);   // scores already include log2e
            s += e;
            Ps[r][lane + c * 32] = e;
        }
#pragma unroll
        for (int o = 16; o; o >>= 1) s += __shfl_xor_sync(0xffffffffu, s, o);
        if (lane == 0) linv[r] = 1.0f / s;
    }
    __syncthreads();

    int d = threadIdx.x & 127;
    int ig = threadIdx.x >> 7;   // 0 -> rows 0..3, 1 -> rows 4..7
    const float* xb = x + (size_t)bb * Lx * Dx;

    float acc[4] = {0.f, 0.f, 0.f, 0.f};

    for (int j = 0; j < Lx; j += 4) {
        float xv0 = xb[(size_t)(j + 0) * Dx + d];
        float xv1 = xb[(size_t)(j + 1) * Dx + d];
        float xv2 = xb[(size_t)(j + 2) * Dx + d];
        float xv3 = xb[(size_t)(j + 3) * Dx + d];
#pragma unroll
        for (int r = 0; r < 4; r++) {
            float4 p = *(const float4*)&Ps[ig * 4 + r][j];
            acc[r] += p.x * xv0 + p.y * xv1 + p.z * xv2 + p.w * xv3;
        }
    }

#pragma unroll
    for (int r = 0; r < 4; r++) {
        int row = row0 + ig * 4 + r;
        out[(size_t)row * Dx + d] = acc[r] * linv[ig * 4 + r];
    }
}

// ---------------------------------------------------------------------------
extern "C" void kernel_launch(void* const* d_in, const int* in_sizes, int n_in,
                              void* d_out, int out_size) {
    const float* x  = (const float*)d_in[0];
    // d_in[1] = mask (bool) — intentionally unused: reference's masked_fill is
    // out-of-place and discarded, so mask has no effect on the output.
    const float* Wq = (const float*)d_in[2];
    const float* bq = (const float*)d_in[3];
    const float* Wk = (const float*)d_in[4];
    const float* bk = (const float*)d_in[5];
    const float* w  = (const float*)d_in[6];
    // d_in[7] = bw — unused: constant score shift cancels in softmax.
    float* out = (float*)d_out;

    dim3 g1(Bx * Lx / 16, 2);
    qk_kernel<<<g1, 256>>>(x, Wq, bq, Wk, bk, w);

    dim3 g2(Lx / 32, Lx / 16, Bx);
    score_kernel<<<g2, 256>>>();

    out_kernel<<<Bx * Lx / 8, 256>>>(x, out);
}

// round 7
// speedup vs baseline: 1.0863x; 1.0863x over previous
#include <cuda_runtime.h>
#include <cuda_fp16.h>

#define Bx 4
#define Lx 512
#define Dx 128
#define NH 12              // harmonics m = 1,3,...,23
#define KP (NH * 2 * Dx)   // 3072 feature dim
#define LOG2E 1.4426950408889634f
#define OMEGA1 0.22439948f // pi/14

// Scratch (static device arrays: allowed; no allocations anywhere)
__device__ float g_Q[Bx * Lx * Dx];               // q projection (pre-tanh)
__device__ float g_K[Bx * Lx * Dx];
__device__ uint4 g_FQ4[(size_t)Bx * Lx * KP / 8]; // f16 features, 16B aligned
__device__ uint4 g_FK4[(size_t)Bx * Lx * KP / 8];
__device__ float g_S[(size_t)Bx * Lx * Lx];

// Fourier sine coefficients of mirrored tanh: b_m = pi / (7 sinh(m pi^2/28))
__device__ __constant__ float c_B[NH] = {
    1.24737f,     0.354585f,   0.158755f,   0.0766902f,
    0.0376905f,   0.0186002f,  0.00918841f, 0.00454012f,
    0.00224348f,  0.00110862f, 0.000547829f, 0.000270714f
};

__device__ __forceinline__ unsigned saddr(const void* p) {
    return (unsigned)__cvta_generic_to_shared(p);
}
__device__ __forceinline__ void cp16(unsigned dst, const void* src) {
    asm volatile("cp.async.cg.shared.global [%0], [%1], 16;" :: "r"(dst), "l"(src));
}
__device__ __forceinline__ void ldsm_x4(unsigned& r0, unsigned& r1, unsigned& r2,
                                        unsigned& r3, unsigned addr) {
    asm volatile("ldmatrix.sync.aligned.m8n8.x4.shared.b16 {%0,%1,%2,%3}, [%4];"
                 : "=r"(r0), "=r"(r1), "=r"(r2), "=r"(r3) : "r"(addr));
}
__device__ __forceinline__ void mma16816(float* c, const unsigned* a,
                                         unsigned b0, unsigned b1) {
    asm volatile(
        "mma.sync.aligned.m16n8k16.row.col.f32.f16.f16.f32 "
        "{%0,%1,%2,%3}, {%4,%5,%6,%7}, {%8,%9}, {%0,%1,%2,%3};"
        : "+f"(c[0]), "+f"(c[1]), "+f"(c[2]), "+f"(c[3])
        : "r"(a[0]), "r"(a[1]), "r"(a[2]), "r"(a[3]), "r"(b0), "r"(b1));
}

// ---------------------------------------------------------------------------
// Kernel 1: projections q = x Wq^T + bq, k = x Wk^T + bk (plain f32 store).
// ---------------------------------------------------------------------------
__global__ __launch_bounds__(256) void qk_kernel(
        const float* __restrict__ x,
        const float* __restrict__ Wq, const float* __restrict__ bq,
        const float* __restrict__ Wk, const float* __restrict__ bk) {
    __shared__ float Wsh[32][130];
    __shared__ float xsh[32][20];

    int which = blockIdx.y;
    int row0 = blockIdx.x * 16;
    const float* W = which ? Wk : Wq;
    const float* bias = which ? bk : bq;
    float* outp = which ? g_K : g_Q;

    int tid = threadIdx.x;
    int e0 = 2 * (tid & 63);
    int rg = tid >> 6;

    const float4* W4 = (const float4*)W;
    const float4* x4 = (const float4*)(x + (size_t)row0 * Dx);

    float acc[4][2];
#pragma unroll
    for (int r = 0; r < 4; r++) { acc[r][0] = 0.f; acc[r][1] = 0.f; }

    for (int c = 0; c < 4; c++) {
        int dc4 = c * 8;
        __syncthreads();
#pragma unroll
        for (int k = 0; k < 4; k++) {
            int idx = tid + 256 * k;
            int e = idx >> 3, j4 = idx & 7;
            float4 v = W4[(size_t)e * 32 + dc4 + j4];
            Wsh[4 * j4 + 0][e] = v.x;
            Wsh[4 * j4 + 1][e] = v.y;
            Wsh[4 * j4 + 2][e] = v.z;
            Wsh[4 * j4 + 3][e] = v.w;
        }
        if (tid < 128) {
            int r = tid >> 3, j4 = tid & 7;
            float4 v = x4[(size_t)r * 32 + dc4 + j4];
            xsh[4 * j4 + 0][r] = v.x;
            xsh[4 * j4 + 1][r] = v.y;
            xsh[4 * j4 + 2][r] = v.z;
            xsh[4 * j4 + 3][r] = v.w;
        }
        __syncthreads();

#pragma unroll
        for (int d = 0; d < 32; d++) {
            float2 wv = *(const float2*)&Wsh[d][e0];
            float4 xv = *(const float4*)&xsh[d][4 * rg];
            acc[0][0] += wv.x * xv.x;  acc[0][1] += wv.y * xv.x;
            acc[1][0] += wv.x * xv.y;  acc[1][1] += wv.y * xv.y;
            acc[2][0] += wv.x * xv.z;  acc[2][1] += wv.y * xv.z;
            acc[3][0] += wv.x * xv.w;  acc[3][1] += wv.y * xv.w;
        }
    }

    float b0 = bias[e0], b1 = bias[e0 + 1];
#pragma unroll
    for (int r = 0; r < 4; r++) {
        int row = row0 + 4 * rg + r;
        *(float2*)&outp[(size_t)row * Dx + e0] =
            make_float2(acc[r][0] + b0, acc[r][1] + b1);
    }
}

// ---------------------------------------------------------------------------
// Kernel 2: Fourier features.
// Q side: FQ[row][h*256 + 2d]   = b_h * w'_d * sin(w_h q),  +1 = ... * cos
// K side: FK[row][h*256 + 2d]   = cos(w_h k),               +1 = sin(w_h k)
// so dot(FQ_i, FK_j) = sum_{d,h} b_h w'_d sin(w_h (q+k)) ~= sum_d w'_d tanh(q+k)
// Harmonics by angle-addition recurrence from (sin,cos)(w1 z).
// ---------------------------------------------------------------------------
__global__ __launch_bounds__(128) void feat_kernel(const float* __restrict__ w) {
    __shared__ unsigned sbuf[4][NH * Dx];   // [row][h*128+d] half2 words, 24KB

    int which = blockIdx.y;
    int row0 = blockIdx.x * 4;
    const float* P = which ? g_K : g_Q;
    uint4* F4 = which ? g_FK4 : g_FQ4;

    int d = threadIdx.x;
    float wp = w[d] * LOG2E;   // only used on q side

#pragma unroll
    for (int r = 0; r < 4; r++) {
        float z = P[(size_t)(row0 + r) * Dx + d];
        float s1, c1;
        __sincosf(OMEGA1 * z, &s1, &c1);
        float s2 = 2.f * s1 * c1;
        float c2 = fmaf(-2.f * s1, s1, 1.f);
        float sm = s1, cm = c1;
#pragma unroll
        for (int h = 0; h < NH; h++) {
            __half2 hv;
            if (which == 0) {
                float sc = c_B[h] * wp;
                hv = __floats2half2_rn(sc * sm, sc * cm);
            } else {
                hv = __floats2half2_rn(cm, sm);
            }
            sbuf[r][h * Dx + d] = *(unsigned*)&hv;
            float ns = fmaf(sm, c2, cm * s2);
            float nc = fmaf(cm, c2, -sm * s2);
            sm = ns; cm = nc;
        }
    }
    __syncthreads();

    // coalesced copy: 4 rows x 384 uint4
    const uint4* sb4 = (const uint4*)sbuf;
    for (int i = threadIdx.x; i < 4 * (KP / 8); i += 128) {
        int r = i / (KP / 8), off = i % (KP / 8);
        F4[(size_t)(row0 + r) * (KP / 8) + off] = sb4[i];
    }
}

// ---------------------------------------------------------------------------
// Kernel 3: S = FQ @ FK^T per batch (f16 HMMA, fp32 accum).
// Block tile 128m x 64n, BK=32, 256 threads (8 warps 4x2), warp tile 32x32.
// cp.async double-buffered; ldmatrix with pad-40 (conflict-free) smem.
// ---------------------------------------------------------------------------
__global__ __launch_bounds__(256) void gemm_kernel() {
    __shared__ __half As[2][128][40];   // 20.0 KB
    __shared__ __half Bs[2][64][40];    // 10.0 KB

    int b = blockIdx.z;
    int i0 = blockIdx.y * 128;
    int j0 = blockIdx.x * 64;
    const __half* FQ = (const __half*)g_FQ4 + ((size_t)b * Lx + i0) * KP;
    const __half* FK = (const __half*)g_FK4 + ((size_t)b * Lx + j0) * KP;

    int tid = threadIdx.x;
    int warp = tid >> 5, lane = tid & 31;
    int wr = warp >> 1, wc = warp & 1;

    float acc[2][4][4];
#pragma unroll
    for (int mt = 0; mt < 2; mt++)
#pragma unroll
        for (int nt = 0; nt < 4; nt++)
#pragma unroll
            for (int q = 0; q < 4; q++) acc[mt][nt][q] = 0.f;

    const int NCH = KP / 32;   // 96 chunks

    // prologue: stage 0
    {
#pragma unroll
        for (int l = 0; l < 2; l++) {
            int idx = tid + 256 * l;
            int row = idx >> 2, seg = idx & 3;
            cp16(saddr(&As[0][row][seg * 8]), FQ + (size_t)row * KP + seg * 8);
        }
        {
            int row = tid >> 2, seg = tid & 3;
            cp16(saddr(&Bs[0][row][seg * 8]), FK + (size_t)row * KP + seg * 8);
        }
        asm volatile("cp.async.commit_group;");
    }

    int buf = 0;
    for (int c = 0; c < NCH; c++) {
        if (c + 1 < NCH) {
            int co = (c + 1) * 32;
#pragma unroll
            for (int l = 0; l < 2; l++) {
                int idx = tid + 256 * l;
                int row = idx >> 2, seg = idx & 3;
                cp16(saddr(&As[buf ^ 1][row][seg * 8]),
                     FQ + (size_t)row * KP + co + seg * 8);
            }
            {
                int row = tid >> 2, seg = tid & 3;
                cp16(saddr(&Bs[buf ^ 1][row][seg * 8]),
                     FK + (size_t)row * KP + co + seg * 8);
            }
            asm volatile("cp.async.commit_group;");
            asm volatile("cp.async.wait_group 1;");
        } else {
            asm volatile("cp.async.wait_group 0;");
        }
        __syncthreads();

#pragma unroll
        for (int ks = 0; ks < 2; ks++) {
            unsigned a[2][4], bb[2][4];
#pragma unroll
            for (int mt = 0; mt < 2; mt++) {
                int row = 32 * wr + 16 * mt + (lane & 7) + 8 * ((lane >> 3) & 1);
                int col = ks * 16 + 8 * (lane >> 4);
                ldsm_x4(a[mt][0], a[mt][1], a[mt][2], a[mt][3],
                        saddr(&As[buf][row][col]));
            }
#pragma unroll
            for (int p = 0; p < 2; p++) {
                int n = 32 * wc + 16 * p + (lane & 7) + 8 * (lane >> 4);
                int col = ks * 16 + 8 * ((lane >> 3) & 1);
                ldsm_x4(bb[p][0], bb[p][1], bb[p][2], bb[p][3],
                        saddr(&Bs[buf][n][col]));
            }
#pragma unroll
            for (int mt = 0; mt < 2; mt++)
#pragma unroll
                for (int nt = 0; nt < 4; nt++)
                    mma16816(acc[mt][nt], a[mt],
                             bb[nt >> 1][2 * (nt & 1)], bb[nt >> 1][2 * (nt & 1) + 1]);
        }
        __syncthreads();
        buf ^= 1;
    }

    float* S = g_S + ((size_t)b * Lx + i0) * Lx + j0;
    int g = lane >> 2, tg = lane & 3;
#pragma unroll
    for (int mt = 0; mt < 2; mt++)
#pragma unroll
        for (int nt = 0; nt < 4; nt++) {
            int r = 32 * wr + 16 * mt + g;
            int cc = 32 * wc + 8 * nt + 2 * tg;
            *(float2*)&S[(size_t)r * Lx + cc] =
                make_float2(acc[mt][nt][0], acc[mt][nt][1]);
            *(float2*)&S[(size_t)(r + 8) * Lx + cc] =
                make_float2(acc[mt][nt][2], acc[mt][nt][3]);
        }
}

// ---------------------------------------------------------------------------
// Kernel 4: softmax over j (scores pre-scaled by log2e -> exp2 direct)
// + out = attn @ x. 8 query rows per block (grid 256), 256 threads.
// ---------------------------------------------------------------------------
__global__ __launch_bounds__(256) void out_kernel(const float* __restrict__ x,
                                                  float* __restrict__ out) {
    __shared__ float Ps[8][Lx];
    __shared__ float linv[8];

    int row0 = blockIdx.x * 8;
    int bb = row0 >> 9;

    const float4* S4 = (const float4*)(g_S + (size_t)row0 * Lx);
    for (int t = threadIdx.x; t < 8 * Lx / 4; t += 256)
        ((float4*)Ps)[t] = S4[t];
    __syncthreads();

    int warp = threadIdx.x >> 5;
    int lane = threadIdx.x & 31;
    {
        int r = warp;
        float v[16];
        float m = -1e30f;
#pragma unroll
        for (int c = 0; c < 16; c++) {
            v[c] = Ps[r][lane + c * 32];
            m = fmaxf(m, v[c]);
        }
#pragma unroll
        for (int o = 16; o; o >>= 1) m = fmaxf(m, __shfl_xor_sync(0xffffffffu, m, o));
        float s = 0.f;
#pragma unroll
        for (int c = 0; c < 16; c++) {
            float e = exp2f(v[c] - m);
            s += e;
            Ps[r][lane + c * 32] = e;
        }
#pragma unroll
        for (int o = 16; o; o >>= 1) s += __shfl_xor_sync(0xffffffffu, s, o);
        if (lane == 0) linv[r] = 1.0f / s;
    }
    __syncthreads();

    int d = threadIdx.x & 127;
    int ig = threadIdx.x >> 7;
    const float* xb = x + (size_t)bb * Lx * Dx;

    float acc[4] = {0.f, 0.f, 0.f, 0.f};

    for (int j = 0; j < Lx; j += 4) {
        float xv0 = xb[(size_t)(j + 0) * Dx + d];
        float xv1 = xb[(size_t)(j + 1) * Dx + d];
        float xv2 = xb[(size_t)(j + 2) * Dx + d];
        float xv3 = xb[(size_t)(j + 3) * Dx + d];
#pragma unroll
        for (int r = 0; r < 4; r++) {
            float4 p = *(const float4*)&Ps[ig * 4 + r][j];
            acc[r] += p.x * xv0 + p.y * xv1 + p.z * xv2 + p.w * xv3;
        }
    }

#pragma unroll
    for (int r = 0; r < 4; r++) {
        int row = row0 + ig * 4 + r;
        out[(size_t)row * Dx + d] = acc[r] * linv[ig * 4 + r];
    }
}

// ---------------------------------------------------------------------------
extern "C" void kernel_launch(void* const* d_in, const int* in_sizes, int n_in,
                              void* d_out, int out_size) {
    const float* x  = (const float*)d_in[0];
    // d_in[1] = mask (bool) — intentionally unused: reference's masked_fill is
    // out-of-place and discarded, so mask has no effect on the output.
    const float* Wq = (const float*)d_in[2];
    const float* bq = (const float*)d_in[3];
    const float* Wk = (const float*)d_in[4];
    const float* bk = (const float*)d_in[5];
    const float* w  = (const float*)d_in[6];
    // d_in[7] = bw — unused: constant score shift cancels in softmax.
    float* out = (float*)d_out;

    dim3 g1(Bx * Lx / 16, 2);
    qk_kernel<<<g1, 256>>>(x, Wq, bq, Wk, bk);

    dim3 gf(Bx * Lx / 4, 2);
    feat_kernel<<<gf, 128>>>(w);

    dim3 gg(Lx / 64, Lx / 128, Bx);
    gemm_kernel<<<gg, 256>>>();

    out_kernel<<<Bx * Lx / 8, 256>>>(x, out);
}

// round 8
// speedup vs baseline: 1.1996x; 1.1043x over previous
#include <cuda_runtime.h>
#include <cuda_fp16.h>

#define Bx 4
#define Lx 512
#define Dx 128
#define NH 12              // harmonics m = 1,3,...,23
#define KP (NH * 2 * Dx)   // 3072 feature dim
#define LOG2E 1.4426950408889634f
#define OMEGA1 0.22439948f // pi/14

// Scratch (static device arrays: allowed; no allocations anywhere)
__device__ float g_Q[Bx * Lx * Dx];               // q projection (pre-tanh)
__device__ float g_K[Bx * Lx * Dx];
__device__ uint4 g_FQ4[(size_t)Bx * Lx * KP / 8]; // f16 features, 16B aligned
__device__ uint4 g_FK4[(size_t)Bx * Lx * KP / 8];
__device__ float g_S[(size_t)Bx * Lx * Lx];

// Fourier sine coefficients of mirrored tanh: b_m = pi / (7 sinh(m pi^2/28))
__device__ __constant__ float c_B[NH] = {
    1.24737f,     0.354585f,   0.158755f,   0.0766902f,
    0.0376905f,   0.0186002f,  0.00918841f, 0.00454012f,
    0.00224348f,  0.00110862f, 0.000547829f, 0.000270714f
};

__device__ __forceinline__ unsigned saddr(const void* p) {
    return (unsigned)__cvta_generic_to_shared(p);
}
__device__ __forceinline__ void cp16(unsigned dst, const void* src) {
    asm volatile("cp.async.cg.shared.global [%0], [%1], 16;" :: "r"(dst), "l"(src));
}
__device__ __forceinline__ void ldsm_x4(unsigned& r0, unsigned& r1, unsigned& r2,
                                        unsigned& r3, unsigned addr) {
    asm volatile("ldmatrix.sync.aligned.m8n8.x4.shared.b16 {%0,%1,%2,%3}, [%4];"
                 : "=r"(r0), "=r"(r1), "=r"(r2), "=r"(r3) : "r"(addr));
}
__device__ __forceinline__ void mma16816(float* c, const unsigned* a,
                                         unsigned b0, unsigned b1) {
    asm volatile(
        "mma.sync.aligned.m16n8k16.row.col.f32.f16.f16.f32 "
        "{%0,%1,%2,%3}, {%4,%5,%6,%7}, {%8,%9}, {%0,%1,%2,%3};"
        : "+f"(c[0]), "+f"(c[1]), "+f"(c[2]), "+f"(c[3])
        : "r"(a[0]), "r"(a[1]), "r"(a[2]), "r"(a[3]), "r"(b0), "r"(b1));
}

// ---------------------------------------------------------------------------
// Kernel 1: projections q = x Wq^T + bq, k = x Wk^T + bk (plain f32 store).
// ---------------------------------------------------------------------------
__global__ __launch_bounds__(256) void qk_kernel(
        const float* __restrict__ x,
        const float* __restrict__ Wq, const float* __restrict__ bq,
        const float* __restrict__ Wk, const float* __restrict__ bk) {
    __shared__ float Wsh[32][130];
    __shared__ float xsh[32][20];

    int which = blockIdx.y;
    int row0 = blockIdx.x * 16;
    const float* W = which ? Wk : Wq;
    const float* bias = which ? bk : bq;
    float* outp = which ? g_K : g_Q;

    int tid = threadIdx.x;
    int e0 = 2 * (tid & 63);
    int rg = tid >> 6;

    const float4* W4 = (const float4*)W;
    const float4* x4 = (const float4*)(x + (size_t)row0 * Dx);

    float acc[4][2];
#pragma unroll
    for (int r = 0; r < 4; r++) { acc[r][0] = 0.f; acc[r][1] = 0.f; }

    for (int c = 0; c < 4; c++) {
        int dc4 = c * 8;
        __syncthreads();
#pragma unroll
        for (int k = 0; k < 4; k++) {
            int idx = tid + 256 * k;
            int e = idx >> 3, j4 = idx & 7;
            float4 v = W4[(size_t)e * 32 + dc4 + j4];
            Wsh[4 * j4 + 0][e] = v.x;
            Wsh[4 * j4 + 1][e] = v.y;
            Wsh[4 * j4 + 2][e] = v.z;
            Wsh[4 * j4 + 3][e] = v.w;
        }
        if (tid < 128) {
            int r = tid >> 3, j4 = tid & 7;
            float4 v = x4[(size_t)r * 32 + dc4 + j4];
            xsh[4 * j4 + 0][r] = v.x;
            xsh[4 * j4 + 1][r] = v.y;
            xsh[4 * j4 + 2][r] = v.z;
            xsh[4 * j4 + 3][r] = v.w;
        }
        __syncthreads();

#pragma unroll
        for (int d = 0; d < 32; d++) {
            float2 wv = *(const float2*)&Wsh[d][e0];
            float4 xv = *(const float4*)&xsh[d][4 * rg];
            acc[0][0] += wv.x * xv.x;  acc[0][1] += wv.y * xv.x;
            acc[1][0] += wv.x * xv.y;  acc[1][1] += wv.y * xv.y;
            acc[2][0] += wv.x * xv.z;  acc[2][1] += wv.y * xv.z;
            acc[3][0] += wv.x * xv.w;  acc[3][1] += wv.y * xv.w;
        }
    }

    float b0 = bias[e0], b1 = bias[e0 + 1];
#pragma unroll
    for (int r = 0; r < 4; r++) {
        int row = row0 + 4 * rg + r;
        *(float2*)&outp[(size_t)row * Dx + e0] =
            make_float2(acc[r][0] + b0, acc[r][1] + b1);
    }
}

// ---------------------------------------------------------------------------
// Kernel 2: Fourier features.
// Q side: FQ[row][h*256 + 2d]   = b_h * w'_d * sin(w_h q),  +1 = ... * cos
// K side: FK[row][h*256 + 2d]   = cos(w_h k),               +1 = sin(w_h k)
// so dot(FQ_i, FK_j) = sum_{d,h} b_h w'_d sin(w_h (q+k)) ~= sum_d w'_d tanh(q+k)
// ---------------------------------------------------------------------------
__global__ __launch_bounds__(128) void feat_kernel(const float* __restrict__ w) {
    __shared__ unsigned sbuf[4][NH * Dx];   // [row][h*128+d] half2 words, 24KB

    int which = blockIdx.y;
    int row0 = blockIdx.x * 4;
    const float* P = which ? g_K : g_Q;
    uint4* F4 = which ? g_FK4 : g_FQ4;

    int d = threadIdx.x;
    float wp = w[d] * LOG2E;   // only used on q side

#pragma unroll
    for (int r = 0; r < 4; r++) {
        float z = P[(size_t)(row0 + r) * Dx + d];
        float s1, c1;
        __sincosf(OMEGA1 * z, &s1, &c1);
        float s2 = 2.f * s1 * c1;
        float c2 = fmaf(-2.f * s1, s1, 1.f);
        float sm = s1, cm = c1;
#pragma unroll
        for (int h = 0; h < NH; h++) {
            __half2 hv;
            if (which == 0) {
                float sc = c_B[h] * wp;
                hv = __floats2half2_rn(sc * sm, sc * cm);
            } else {
                hv = __floats2half2_rn(cm, sm);
            }
            sbuf[r][h * Dx + d] = *(unsigned*)&hv;
            float ns = fmaf(sm, c2, cm * s2);
            float nc = fmaf(cm, c2, -sm * s2);
            sm = ns; cm = nc;
        }
    }
    __syncthreads();

    const uint4* sb4 = (const uint4*)sbuf;
    for (int i = threadIdx.x; i < 4 * (KP / 8); i += 128) {
        int r = i / (KP / 8), off = i % (KP / 8);
        F4[(size_t)(row0 + r) * (KP / 8) + off] = sb4[i];
    }
}

// ---------------------------------------------------------------------------
// Kernel 3: S = FQ @ FK^T per batch (f16 HMMA, fp32 accum).
// Block tile 128m x 64n, BK=32, 256 threads (8 warps 4x2), warp tile 32x32.
// ---------------------------------------------------------------------------
__global__ __launch_bounds__(256) void gemm_kernel() {
    __shared__ __half As[2][128][40];   // 20.0 KB
    __shared__ __half Bs[2][64][40];    // 10.0 KB

    int b = blockIdx.z;
    int i0 = blockIdx.y * 128;
    int j0 = blockIdx.x * 64;
    const __half* FQ = (const __half*)g_FQ4 + ((size_t)b * Lx + i0) * KP;
    const __half* FK = (const __half*)g_FK4 + ((size_t)b * Lx + j0) * KP;

    int tid = threadIdx.x;
    int warp = tid >> 5, lane = tid & 31;
    int wr = warp >> 1, wc = warp & 1;

    float acc[2][4][4];
#pragma unroll
    for (int mt = 0; mt < 2; mt++)
#pragma unroll
        for (int nt = 0; nt < 4; nt++)
#pragma unroll
            for (int q = 0; q < 4; q++) acc[mt][nt][q] = 0.f;

    const int NCH = KP / 32;   // 96 chunks

    {
#pragma unroll
        for (int l = 0; l < 2; l++) {
            int idx = tid + 256 * l;
            int row = idx >> 2, seg = idx & 3;
            cp16(saddr(&As[0][row][seg * 8]), FQ + (size_t)row * KP + seg * 8);
        }
        {
            int row = tid >> 2, seg = tid & 3;
            cp16(saddr(&Bs[0][row][seg * 8]), FK + (size_t)row * KP + seg * 8);
        }
        asm volatile("cp.async.commit_group;");
    }

    int buf = 0;
    for (int c = 0; c < NCH; c++) {
        if (c + 1 < NCH) {
            int co = (c + 1) * 32;
#pragma unroll
            for (int l = 0; l < 2; l++) {
                int idx = tid + 256 * l;
                int row = idx >> 2, seg = idx & 3;
                cp16(saddr(&As[buf ^ 1][row][seg * 8]),
                     FQ + (size_t)row * KP + co + seg * 8);
            }
            {
                int row = tid >> 2, seg = tid & 3;
                cp16(saddr(&Bs[buf ^ 1][row][seg * 8]),
                     FK + (size_t)row * KP + co + seg * 8);
            }
            asm volatile("cp.async.commit_group;");
            asm volatile("cp.async.wait_group 1;");
        } else {
            asm volatile("cp.async.wait_group 0;");
        }
        __syncthreads();

#pragma unroll
        for (int ks = 0; ks < 2; ks++) {
            unsigned a[2][4], bb[2][4];
#pragma unroll
            for (int mt = 0; mt < 2; mt++) {
                int row = 32 * wr + 16 * mt + (lane & 7) + 8 * ((lane >> 3) & 1);
                int col = ks * 16 + 8 * (lane >> 4);
                ldsm_x4(a[mt][0], a[mt][1], a[mt][2], a[mt][3],
                        saddr(&As[buf][row][col]));
            }
#pragma unroll
            for (int p = 0; p < 2; p++) {
                int n = 32 * wc + 16 * p + (lane & 7) + 8 * (lane >> 4);
                int col = ks * 16 + 8 * ((lane >> 3) & 1);
                ldsm_x4(bb[p][0], bb[p][1], bb[p][2], bb[p][3],
                        saddr(&Bs[buf][n][col]));
            }
#pragma unroll
            for (int mt = 0; mt < 2; mt++)
#pragma unroll
                for (int nt = 0; nt < 4; nt++)
                    mma16816(acc[mt][nt], a[mt],
                             bb[nt >> 1][2 * (nt & 1)], bb[nt >> 1][2 * (nt & 1) + 1]);
        }
        __syncthreads();
        buf ^= 1;
    }

    float* S = g_S + ((size_t)b * Lx + i0) * Lx + j0;
    int g = lane >> 2, tg = lane & 3;
#pragma unroll
    for (int mt = 0; mt < 2; mt++)
#pragma unroll
        for (int nt = 0; nt < 4; nt++) {
            int r = 32 * wr + 16 * mt + g;
            int cc = 32 * wc + 8 * nt + 2 * tg;
            *(float2*)&S[(size_t)r * Lx + cc] =
                make_float2(acc[mt][nt][0], acc[mt][nt][1]);
            *(float2*)&S[(size_t)(r + 8) * Lx + cc] =
                make_float2(acc[mt][nt][2], acc[mt][nt][3]);
        }
}

// ---------------------------------------------------------------------------
// Kernel 4: softmax over j (scores pre-scaled by log2e -> exp2 direct)
// + out = attn @ x, with x staged through smem in 32-j tiles (coalesced
// float4 loads, MLP 4, ~6 blocks/SM overlap staging with compute) instead of
// the R7 scalar-LDG latency chains that made this kernel 60us.
// ---------------------------------------------------------------------------
__global__ __launch_bounds__(256) void out_kernel(const float* __restrict__ x,
                                                  float* __restrict__ out) {
    __shared__ float Ps[8][Lx];       // 16 KB
    __shared__ float xs[32][Dx];      // 16 KB x tile
    __shared__ float linv[8];

    int row0 = blockIdx.x * 8;
    int bb = row0 >> 9;

    const float4* S4 = (const float4*)(g_S + (size_t)row0 * Lx);
    for (int t = threadIdx.x; t < 8 * Lx / 4; t += 256)
        ((float4*)Ps)[t] = S4[t];
    __syncthreads();

    int warp = threadIdx.x >> 5;
    int lane = threadIdx.x & 31;
    {
        int r = warp;
        float v[16];
        float m = -1e30f;
#pragma unroll
        for (int c = 0; c < 16; c++) {
            v[c] = Ps[r][lane + c * 32];
            m = fmaxf(m, v[c]);
        }
#pragma unroll
        for (int o = 16; o; o >>= 1) m = fmaxf(m, __shfl_xor_sync(0xffffffffu, m, o));
        float s = 0.f;
#pragma unroll
        for (int c = 0; c < 16; c++) {
            float e = exp2f(v[c] - m);
            s += e;
            Ps[r][lane + c * 32] = e;
        }
#pragma unroll
        for (int o = 16; o; o >>= 1) s += __shfl_xor_sync(0xffffffffu, s, o);
        if (lane == 0) linv[r] = 1.0f / s;
    }

    int d = threadIdx.x & 127;
    int ig = threadIdx.x >> 7;   // 0 -> rows 0..3, 1 -> rows 4..7
    const float4* xb4 = (const float4*)(x + (size_t)bb * Lx * Dx);

    float acc[4] = {0.f, 0.f, 0.f, 0.f};

    for (int jt = 0; jt < Lx; jt += 32) {
        __syncthreads();   // Ps ready (first iter) / prior tile consumed
        // stage 32 x 128 floats = 1024 float4; 4 per thread, coalesced
#pragma unroll
        for (int t = 0; t < 4; t++) {
            int idx = threadIdx.x + 256 * t;
            ((float4*)xs)[idx] = xb4[jt * 32 + idx];
        }
        __syncthreads();

#pragma unroll
        for (int j4 = 0; j4 < 8; j4++) {
            float xv0 = xs[4 * j4 + 0][d];
            float xv1 = xs[4 * j4 + 1][d];
            float xv2 = xs[4 * j4 + 2][d];
            float xv3 = xs[4 * j4 + 3][d];
#pragma unroll
            for (int r = 0; r < 4; r++) {
                float4 p = *(const float4*)&Ps[ig * 4 + r][jt + 4 * j4];
                acc[r] = fmaf(p.x, xv0, acc[r]);
                acc[r] = fmaf(p.y, xv1, acc[r]);
                acc[r] = fmaf(p.z, xv2, acc[r]);
                acc[r] = fmaf(p.w, xv3, acc[r]);
            }
        }
    }

#pragma unroll
    for (int r = 0; r < 4; r++) {
        int row = row0 + ig * 4 + r;
        out[(size_t)row * Dx + d] = acc[r] * linv[ig * 4 + r];
    }
}

// ---------------------------------------------------------------------------
extern "C" void kernel_launch(void* const* d_in, const int* in_sizes, int n_in,
                              void* d_out, int out_size) {
    const float* x  = (const float*)d_in[0];
    // d_in[1] = mask (bool) — intentionally unused: reference's masked_fill is
    // out-of-place and discarded, so mask has no effect on the output.
    const float* Wq = (const float*)d_in[2];
    const float* bq = (const float*)d_in[3];
    const float* Wk = (const float*)d_in[4];
    const float* bk = (const float*)d_in[5];
    const float* w  = (const float*)d_in[6];
    // d_in[7] = bw — unused: constant score shift cancels in softmax.
    float* out = (float*)d_out;

    dim3 g1(Bx * Lx / 16, 2);
    qk_kernel<<<g1, 256>>>(x, Wq, bq, Wk, bk);

    dim3 gf(Bx * Lx / 4, 2);
    feat_kernel<<<gf, 128>>>(w);

    dim3 gg(Lx / 64, Lx / 128, Bx);
    gemm_kernel<<<gg, 256>>>();

    out_kernel<<<Bx * Lx / 8, 256>>>(x, out);
}

// round 9
// speedup vs baseline: 1.2517x; 1.0434x over previous
#include <cuda_runtime.h>
#include <cuda_fp16.h>

#define Bx 4
#define Lx 512
#define Dx 128
#define NH 12              // harmonics m = 1,3,...,23
#define KP (NH * 2 * Dx)   // 3072 feature dim
#define LOG2E 1.4426950408889634f
#define OMEGA1 0.22439948f // pi/14

// Scratch (static device arrays: allowed; no allocations anywhere)
__device__ float g_Q[Bx * Lx * Dx];               // q projection (pre-tanh)
__device__ float g_K[Bx * Lx * Dx];
__device__ uint4 g_FQ4[(size_t)Bx * Lx * KP / 8]; // f16 features, 16B aligned
__device__ uint4 g_FK4[(size_t)Bx * Lx * KP / 8];
__device__ float g_S[(size_t)Bx * Lx * Lx];

// Fourier sine coefficients of mirrored tanh: b_m = pi / (7 sinh(m pi^2/28))
__device__ __constant__ float c_B[NH] = {
    1.24737f,     0.354585f,   0.158755f,   0.0766902f,
    0.0376905f,   0.0186002f,  0.00918841f, 0.00454012f,
    0.00224348f,  0.00110862f, 0.000547829f, 0.000270714f
};

__device__ __forceinline__ unsigned saddr(const void* p) {
    return (unsigned)__cvta_generic_to_shared(p);
}
__device__ __forceinline__ void cp16(unsigned dst, const void* src) {
    asm volatile("cp.async.cg.shared.global [%0], [%1], 16;" :: "r"(dst), "l"(src));
}
__device__ __forceinline__ void ldsm_x4(unsigned& r0, unsigned& r1, unsigned& r2,
                                        unsigned& r3, unsigned addr) {
    asm volatile("ldmatrix.sync.aligned.m8n8.x4.shared.b16 {%0,%1,%2,%3}, [%4];"
                 : "=r"(r0), "=r"(r1), "=r"(r2), "=r"(r3) : "r"(addr));
}
__device__ __forceinline__ void mma16816(float* c, const unsigned* a,
                                         unsigned b0, unsigned b1) {
    asm volatile(
        "mma.sync.aligned.m16n8k16.row.col.f32.f16.f16.f32 "
        "{%0,%1,%2,%3}, {%4,%5,%6,%7}, {%8,%9}, {%0,%1,%2,%3};"
        : "+f"(c[0]), "+f"(c[1]), "+f"(c[2]), "+f"(c[3])
        : "r"(a[0]), "r"(a[1]), "r"(a[2]), "r"(a[3]), "r"(b0), "r"(b1));
}

// ---------------------------------------------------------------------------
// Kernel 1: projections q = x Wq^T + bq, k = x Wk^T + bk.
// Register-prefetch pipeline: while chunk c is consumed from smem, chunk c+1
// is already in flight to registers (LDG latency overlapped with FFMA block).
// ---------------------------------------------------------------------------
__global__ __launch_bounds__(256) void qk_kernel(
        const float* __restrict__ x,
        const float* __restrict__ Wq, const float* __restrict__ bq,
        const float* __restrict__ Wk, const float* __restrict__ bk) {
    __shared__ float Wsh[32][130];
    __shared__ float xsh[32][20];

    int which = blockIdx.y;
    int row0 = blockIdx.x * 16;
    const float* W = which ? Wk : Wq;
    const float* bias = which ? bk : bq;
    float* outp = which ? g_K : g_Q;

    int tid = threadIdx.x;
    int e0 = 2 * (tid & 63);
    int rg = tid >> 6;

    const float4* W4 = (const float4*)W;
    const float4* x4 = (const float4*)(x + (size_t)row0 * Dx);

    // prefetch chunk 0 into registers
    float4 wreg[4];
    float4 xreg;
#pragma unroll
    for (int k = 0; k < 4; k++) {
        int idx = tid + 256 * k;
        wreg[k] = W4[(size_t)(idx >> 3) * 32 + (idx & 7)];
    }
    if (tid < 128) xreg = x4[(size_t)(tid >> 3) * 32 + (tid & 7)];

    float acc[4][2];
#pragma unroll
    for (int r = 0; r < 4; r++) { acc[r][0] = 0.f; acc[r][1] = 0.f; }

    for (int c = 0; c < 4; c++) {
        __syncthreads();   // previous compute done
#pragma unroll
        for (int k = 0; k < 4; k++) {
            int idx = tid + 256 * k;
            int e = idx >> 3, j4 = idx & 7;
            Wsh[4 * j4 + 0][e] = wreg[k].x;
            Wsh[4 * j4 + 1][e] = wreg[k].y;
            Wsh[4 * j4 + 2][e] = wreg[k].z;
            Wsh[4 * j4 + 3][e] = wreg[k].w;
        }
        if (tid < 128) {
            int r = tid >> 3, j4 = tid & 7;
            xsh[4 * j4 + 0][r] = xreg.x;
            xsh[4 * j4 + 1][r] = xreg.y;
            xsh[4 * j4 + 2][r] = xreg.z;
            xsh[4 * j4 + 3][r] = xreg.w;
        }
        __syncthreads();

        if (c < 3) {       // issue next-chunk loads; latency hidden by compute
            int dc4n = (c + 1) * 8;
#pragma unroll
            for (int k = 0; k < 4; k++) {
                int idx = tid + 256 * k;
                wreg[k] = W4[(size_t)(idx >> 3) * 32 + dc4n + (idx & 7)];
            }
            if (tid < 128) xreg = x4[(size_t)(tid >> 3) * 32 + dc4n + (tid & 7)];
        }

#pragma unroll
        for (int d = 0; d < 32; d++) {
            float2 wv = *(const float2*)&Wsh[d][e0];
            float4 xv = *(const float4*)&xsh[d][4 * rg];
            acc[0][0] += wv.x * xv.x;  acc[0][1] += wv.y * xv.x;
            acc[1][0] += wv.x * xv.y;  acc[1][1] += wv.y * xv.y;
            acc[2][0] += wv.x * xv.z;  acc[2][1] += wv.y * xv.z;
            acc[3][0] += wv.x * xv.w;  acc[3][1] += wv.y * xv.w;
        }
    }

    float b0 = bias[e0], b1 = bias[e0 + 1];
#pragma unroll
    for (int r = 0; r < 4; r++) {
        int row = row0 + 4 * rg + r;
        *(float2*)&outp[(size_t)row * Dx + e0] =
            make_float2(acc[r][0] + b0, acc[r][1] + b1);
    }
}

// ---------------------------------------------------------------------------
// Kernel 2: Fourier features.
// Q side: FQ[row][h*256 + 2d]   = b_h * w'_d * sin(w_h q),  +1 = ... * cos
// K side: FK[row][h*256 + 2d]   = cos(w_h k),               +1 = sin(w_h k)
// ---------------------------------------------------------------------------
__global__ __launch_bounds__(128) void feat_kernel(const float* __restrict__ w) {
    __shared__ unsigned sbuf[4][NH * Dx];   // [row][h*128+d] half2 words, 24KB

    int which = blockIdx.y;
    int row0 = blockIdx.x * 4;
    const float* P = which ? g_K : g_Q;
    uint4* F4 = which ? g_FK4 : g_FQ4;

    int d = threadIdx.x;
    float wp = w[d] * LOG2E;   // only used on q side

#pragma unroll
    for (int r = 0; r < 4; r++) {
        float z = P[(size_t)(row0 + r) * Dx + d];
        float s1, c1;
        __sincosf(OMEGA1 * z, &s1, &c1);
        float s2 = 2.f * s1 * c1;
        float c2 = fmaf(-2.f * s1, s1, 1.f);
        float sm = s1, cm = c1;
#pragma unroll
        for (int h = 0; h < NH; h++) {
            __half2 hv;
            if (which == 0) {
                float sc = c_B[h] * wp;
                hv = __floats2half2_rn(sc * sm, sc * cm);
            } else {
                hv = __floats2half2_rn(cm, sm);
            }
            sbuf[r][h * Dx + d] = *(unsigned*)&hv;
            float ns = fmaf(sm, c2, cm * s2);
            float nc = fmaf(cm, c2, -sm * s2);
            sm = ns; cm = nc;
        }
    }
    __syncthreads();

    const uint4* sb4 = (const uint4*)sbuf;
    for (int i = threadIdx.x; i < 4 * (KP / 8); i += 128) {
        int r = i / (KP / 8), off = i % (KP / 8);
        F4[(size_t)(row0 + r) * (KP / 8) + off] = sb4[i];
    }
}

// ---------------------------------------------------------------------------
// Kernel 3: S = FQ @ FK^T per batch (f16 HMMA, fp32 accum).
// Block tile 128m x 64n, BK=32, 256 threads (8 warps 4x2), warp tile 32x32.
// ---------------------------------------------------------------------------
__global__ __launch_bounds__(256) void gemm_kernel() {
    __shared__ __half As[2][128][40];   // 20.0 KB
    __shared__ __half Bs[2][64][40];    // 10.0 KB

    int b = blockIdx.z;
    int i0 = blockIdx.y * 128;
    int j0 = blockIdx.x * 64;
    const __half* FQ = (const __half*)g_FQ4 + ((size_t)b * Lx + i0) * KP;
    const __half* FK = (const __half*)g_FK4 + ((size_t)b * Lx + j0) * KP;

    int tid = threadIdx.x;
    int warp = tid >> 5, lane = tid & 31;
    int wr = warp >> 1, wc = warp & 1;

    float acc[2][4][4];
#pragma unroll
    for (int mt = 0; mt < 2; mt++)
#pragma unroll
        for (int nt = 0; nt < 4; nt++)
#pragma unroll
            for (int q = 0; q < 4; q++) acc[mt][nt][q] = 0.f;

    const int NCH = KP / 32;   // 96 chunks

    {
#pragma unroll
        for (int l = 0; l < 2; l++) {
            int idx = tid + 256 * l;
            int row = idx >> 2, seg = idx & 3;
            cp16(saddr(&As[0][row][seg * 8]), FQ + (size_t)row * KP + seg * 8);
        }
        {
            int row = tid >> 2, seg = tid & 3;
            cp16(saddr(&Bs[0][row][seg * 8]), FK + (size_t)row * KP + seg * 8);
        }
        asm volatile("cp.async.commit_group;");
    }

    int buf = 0;
    for (int c = 0; c < NCH; c++) {
        if (c + 1 < NCH) {
            int co = (c + 1) * 32;
#pragma unroll
            for (int l = 0; l < 2; l++) {
                int idx = tid + 256 * l;
                int row = idx >> 2, seg = idx & 3;
                cp16(saddr(&As[buf ^ 1][row][seg * 8]),
                     FQ + (size_t)row * KP + co + seg * 8);
            }
            {
                int row = tid >> 2, seg = tid & 3;
                cp16(saddr(&Bs[buf ^ 1][row][seg * 8]),
                     FK + (size_t)row * KP + co + seg * 8);
            }
            asm volatile("cp.async.commit_group;");
            asm volatile("cp.async.wait_group 1;");
        } else {
            asm volatile("cp.async.wait_group 0;");
        }
        __syncthreads();

#pragma unroll
        for (int ks = 0; ks < 2; ks++) {
            unsigned a[2][4], bb[2][4];
#pragma unroll
            for (int mt = 0; mt < 2; mt++) {
                int row = 32 * wr + 16 * mt + (lane & 7) + 8 * ((lane >> 3) & 1);
                int col = ks * 16 + 8 * (lane >> 4);
                ldsm_x4(a[mt][0], a[mt][1], a[mt][2], a[mt][3],
                        saddr(&As[buf][row][col]));
            }
#pragma unroll
            for (int p = 0; p < 2; p++) {
                int n = 32 * wc + 16 * p + (lane & 7) + 8 * (lane >> 4);
                int col = ks * 16 + 8 * ((lane >> 3) & 1);
                ldsm_x4(bb[p][0], bb[p][1], bb[p][2], bb[p][3],
                        saddr(&Bs[buf][n][col]));
            }
#pragma unroll
            for (int mt = 0; mt < 2; mt++)
#pragma unroll
                for (int nt = 0; nt < 4; nt++)
                    mma16816(acc[mt][nt], a[mt],
                             bb[nt >> 1][2 * (nt & 1)], bb[nt >> 1][2 * (nt & 1) + 1]);
        }
        __syncthreads();
        buf ^= 1;
    }

    float* S = g_S + ((size_t)b * Lx + i0) * Lx + j0;
    int g = lane >> 2, tg = lane & 3;
#pragma unroll
    for (int mt = 0; mt < 2; mt++)
#pragma unroll
        for (int nt = 0; nt < 4; nt++) {
            int r = 32 * wr + 16 * mt + g;
            int cc = 32 * wc + 8 * nt + 2 * tg;
            *(float2*)&S[(size_t)r * Lx + cc] =
                make_float2(acc[mt][nt][0], acc[mt][nt][1]);
            *(float2*)&S[(size_t)(r + 8) * Lx + cc] =
                make_float2(acc[mt][nt][2], acc[mt][nt][3]);
        }
}

// ---------------------------------------------------------------------------
// Kernel 4: softmax + out = attn @ x, cp.async double-buffered x tiles
// (16 j-rows per tile). Tiles 0,1 issued BEFORE softmax so the softmax hides
// the initial load latency; thereafter tile it+1 is in flight during compute
// of tile it (wait_group 1, uniform empty commits at the tail).
// ---------------------------------------------------------------------------
__global__ __launch_bounds__(256) void out_kernel(const float* __restrict__ x,
                                                  float* __restrict__ out) {
    __shared__ float Ps[8][Lx];          // 16 KB
    __shared__ float xs[2][16][Dx];      // 16 KB (two 8KB tiles)
    __shared__ float linv[8];

    int row0 = blockIdx.x * 8;
    int bb = row0 >> 9;
    const float* xb = x + (size_t)bb * Lx * Dx;

    // issue x tiles 0 and 1 (each 16x128 f32 = 512 float4, 2 per thread)
#pragma unroll
    for (int t = 0; t < 2; t++) {
        int idx = threadIdx.x + 256 * t;
        cp16(saddr(&((float*)xs[0])[idx * 4]), xb + idx * 4);
    }
    asm volatile("cp.async.commit_group;");
#pragma unroll
    for (int t = 0; t < 2; t++) {
        int idx = threadIdx.x + 256 * t;
        cp16(saddr(&((float*)xs[1])[idx * 4]), xb + 16 * Dx + idx * 4);
    }
    asm volatile("cp.async.commit_group;");

    // stage S and softmax (overlaps with x tile loads)
    const float4* S4 = (const float4*)(g_S + (size_t)row0 * Lx);
    for (int t = threadIdx.x; t < 8 * Lx / 4; t += 256)
        ((float4*)Ps)[t] = S4[t];
    __syncthreads();

    int warp = threadIdx.x >> 5;
    int lane = threadIdx.x & 31;
    {
        int r = warp;
        float v[16];
        float m = -1e30f;
#pragma unroll
        for (int c = 0; c < 16; c++) {
            v[c] = Ps[r][lane + c * 32];
            m = fmaxf(m, v[c]);
        }
#pragma unroll
        for (int o = 16; o; o >>= 1) m = fmaxf(m, __shfl_xor_sync(0xffffffffu, m, o));
        float s = 0.f;
#pragma unroll
        for (int c = 0; c < 16; c++) {
            float e = exp2f(v[c] - m);   // scores already include log2e
            s += e;
            Ps[r][lane + c * 32] = e;
        }
#pragma unroll
        for (int o = 16; o; o >>= 1) s += __shfl_xor_sync(0xffffffffu, s, o);
        if (lane == 0) linv[r] = 1.0f / s;
    }

    int d = threadIdx.x & 127;
    int ig = threadIdx.x >> 7;   // 0 -> rows 0..3, 1 -> rows 4..7

    float acc[4] = {0.f, 0.f, 0.f, 0.f};

    for (int it = 0; it < 32; it++) {
        asm volatile("cp.async.wait_group 1;");
        __syncthreads();   // tile `it` visible to all; Ps ready (first iter)

        int buf = it & 1;
        int jt = it * 16;
#pragma unroll
        for (int j4 = 0; j4 < 4; j4++) {
            float xv0 = xs[buf][4 * j4 + 0][d];
            float xv1 = xs[buf][4 * j4 + 1][d];
            float xv2 = xs[buf][4 * j4 + 2][d];
            float xv3 = xs[buf][4 * j4 + 3][d];
#pragma unroll
            for (int r = 0; r < 4; r++) {
                float4 p = *(const float4*)&Ps[ig * 4 + r][jt + 4 * j4];
                acc[r] = fmaf(p.x, xv0, acc[r]);
                acc[r] = fmaf(p.y, xv1, acc[r]);
                acc[r] = fmaf(p.z, xv2, acc[r]);
                acc[r] = fmaf(p.w, xv3, acc[r]);
            }
        }
        __syncthreads();   // tile consumed; safe to overwrite buffer

        if (it + 2 < 32) {
#pragma unroll
            for (int t = 0; t < 2; t++) {
                int idx = threadIdx.x + 256 * t;
                cp16(saddr(&((float*)xs[buf])[idx * 4]),
                     xb + (size_t)(it + 2) * 16 * Dx + idx * 4);
            }
        }
        asm volatile("cp.async.commit_group;");   // uniform group count
    }

#pragma unroll
    for (int r = 0; r < 4; r++) {
        int row = row0 + ig * 4 + r;
        out[(size_t)row * Dx + d] = acc[r] * linv[ig * 4 + r];
    }
}

// ---------------------------------------------------------------------------
extern "C" void kernel_launch(void* const* d_in, const int* in_sizes, int n_in,
                              void* d_out, int out_size) {
    const float* x  = (const float*)d_in[0];
    // d_in[1] = mask (bool) — intentionally unused: reference's masked_fill is
    // out-of-place and discarded, so mask has no effect on the output.
    const float* Wq = (const float*)d_in[2];
    const float* bq = (const float*)d_in[3];
    const float* Wk = (const float*)d_in[4];
    const float* bk = (const float*)d_in[5];
    const float* w  = (const float*)d_in[6];
    // d_in[7] = bw — unused: constant score shift cancels in softmax.
    float* out = (float*)d_out;

    dim3 g1(Bx * Lx / 16, 2);
    qk_kernel<<<g1, 256>>>(x, Wq, bq, Wk, bk);

    dim3 gf(Bx * Lx / 4, 2);
    feat_kernel<<<gf, 128>>>(w);

    dim3 gg(Lx / 64, Lx / 128, Bx);
    gemm_kernel<<<gg, 256>>>();

    out_kernel<<<Bx * Lx / 8, 256>>>(x, out);
}

// round 10
// speedup vs baseline: 1.2615x; 1.0078x over previous
#include <cuda_runtime.h>
#include <cuda_fp16.h>

#define Bx 4
#define Lx 512
#define Dx 128
#define NH 12              // harmonics m = 1,3,...,23
#define KP (NH * 2 * Dx)   // 3072 feature dim
#define KH (KP / 2)        // split-K half
#define LOG2E 1.4426950408889634f
#define OMEGA1 0.22439948f // pi/14

// Scratch (static device arrays: allowed; no allocations anywhere)
__device__ float g_Q[Bx * Lx * Dx];               // q projection (pre-tanh)
__device__ float g_K[Bx * Lx * Dx];
__device__ uint4 g_FQ4[(size_t)Bx * Lx * KP / 8]; // f16 features, 16B aligned
__device__ uint4 g_FK4[(size_t)Bx * Lx * KP / 8];
__device__ float g_S[(size_t)Bx * Lx * Lx];       // split-K partial 0
__device__ float g_S2[(size_t)Bx * Lx * Lx];      // split-K partial 1

// Fourier sine coefficients of mirrored tanh: b_m = pi / (7 sinh(m pi^2/28))
__device__ __constant__ float c_B[NH] = {
    1.24737f,     0.354585f,   0.158755f,   0.0766902f,
    0.0376905f,   0.0186002f,  0.00918841f, 0.00454012f,
    0.00224348f,  0.00110862f, 0.000547829f, 0.000270714f
};

__device__ __forceinline__ unsigned saddr(const void* p) {
    return (unsigned)__cvta_generic_to_shared(p);
}
__device__ __forceinline__ void cp16(unsigned dst, const void* src) {
    asm volatile("cp.async.cg.shared.global [%0], [%1], 16;" :: "r"(dst), "l"(src));
}
__device__ __forceinline__ void ldsm_x4(unsigned& r0, unsigned& r1, unsigned& r2,
                                        unsigned& r3, unsigned addr) {
    asm volatile("ldmatrix.sync.aligned.m8n8.x4.shared.b16 {%0,%1,%2,%3}, [%4];"
                 : "=r"(r0), "=r"(r1), "=r"(r2), "=r"(r3) : "r"(addr));
}
__device__ __forceinline__ void mma16816(float* c, const unsigned* a,
                                         unsigned b0, unsigned b1) {
    asm volatile(
        "mma.sync.aligned.m16n8k16.row.col.f32.f16.f16.f32 "
        "{%0,%1,%2,%3}, {%4,%5,%6,%7}, {%8,%9}, {%0,%1,%2,%3};"
        : "+f"(c[0]), "+f"(c[1]), "+f"(c[2]), "+f"(c[3])
        : "r"(a[0]), "r"(a[1]), "r"(a[2]), "r"(a[3]), "r"(b0), "r"(b1));
}

// ---------------------------------------------------------------------------
// Kernel 1: projections q = x Wq^T + bq, k = x Wk^T + bk.
// Register-prefetch pipeline over 32-d chunks.
// ---------------------------------------------------------------------------
__global__ __launch_bounds__(256) void qk_kernel(
        const float* __restrict__ x,
        const float* __restrict__ Wq, const float* __restrict__ bq,
        const float* __restrict__ Wk, const float* __restrict__ bk) {
    __shared__ float Wsh[32][130];
    __shared__ float xsh[32][20];

    int which = blockIdx.y;
    int row0 = blockIdx.x * 16;
    const float* W = which ? Wk : Wq;
    const float* bias = which ? bk : bq;
    float* outp = which ? g_K : g_Q;

    int tid = threadIdx.x;
    int e0 = 2 * (tid & 63);
    int rg = tid >> 6;

    const float4* W4 = (const float4*)W;
    const float4* x4 = (const float4*)(x + (size_t)row0 * Dx);

    float4 wreg[4];
    float4 xreg;
#pragma unroll
    for (int k = 0; k < 4; k++) {
        int idx = tid + 256 * k;
        wreg[k] = W4[(size_t)(idx >> 3) * 32 + (idx & 7)];
    }
    if (tid < 128) xreg = x4[(size_t)(tid >> 3) * 32 + (tid & 7)];

    float acc[4][2];
#pragma unroll
    for (int r = 0; r < 4; r++) { acc[r][0] = 0.f; acc[r][1] = 0.f; }

    for (int c = 0; c < 4; c++) {
        __syncthreads();
#pragma unroll
        for (int k = 0; k < 4; k++) {
            int idx = tid + 256 * k;
            int e = idx >> 3, j4 = idx & 7;
            Wsh[4 * j4 + 0][e] = wreg[k].x;
            Wsh[4 * j4 + 1][e] = wreg[k].y;
            Wsh[4 * j4 + 2][e] = wreg[k].z;
            Wsh[4 * j4 + 3][e] = wreg[k].w;
        }
        if (tid < 128) {
            int r = tid >> 3, j4 = tid & 7;
            xsh[4 * j4 + 0][r] = xreg.x;
            xsh[4 * j4 + 1][r] = xreg.y;
            xsh[4 * j4 + 2][r] = xreg.z;
            xsh[4 * j4 + 3][r] = xreg.w;
        }
        __syncthreads();

        if (c < 3) {
            int dc4n = (c + 1) * 8;
#pragma unroll
            for (int k = 0; k < 4; k++) {
                int idx = tid + 256 * k;
                wreg[k] = W4[(size_t)(idx >> 3) * 32 + dc4n + (idx & 7)];
            }
            if (tid < 128) xreg = x4[(size_t)(tid >> 3) * 32 + dc4n + (tid & 7)];
        }

#pragma unroll
        for (int d = 0; d < 32; d++) {
            float2 wv = *(const float2*)&Wsh[d][e0];
            float4 xv = *(const float4*)&xsh[d][4 * rg];
            acc[0][0] += wv.x * xv.x;  acc[0][1] += wv.y * xv.x;
            acc[1][0] += wv.x * xv.y;  acc[1][1] += wv.y * xv.y;
            acc[2][0] += wv.x * xv.z;  acc[2][1] += wv.y * xv.z;
            acc[3][0] += wv.x * xv.w;  acc[3][1] += wv.y * xv.w;
        }
    }

    float b0 = bias[e0], b1 = bias[e0 + 1];
#pragma unroll
    for (int r = 0; r < 4; r++) {
        int row = row0 + 4 * rg + r;
        *(float2*)&outp[(size_t)row * Dx + e0] =
            make_float2(acc[r][0] + b0, acc[r][1] + b1);
    }
}

// ---------------------------------------------------------------------------
// Kernel 2: Fourier features.
// Q side: FQ[row][h*256 + 2d]   = b_h * w'_d * sin(w_h q),  +1 = ... * cos
// K side: FK[row][h*256 + 2d]   = cos(w_h k),               +1 = sin(w_h k)
// ---------------------------------------------------------------------------
__global__ __launch_bounds__(128) void feat_kernel(const float* __restrict__ w) {
    __shared__ unsigned sbuf[4][NH * Dx];   // [row][h*128+d] half2 words, 24KB

    int which = blockIdx.y;
    int row0 = blockIdx.x * 4;
    const float* P = which ? g_K : g_Q;
    uint4* F4 = which ? g_FK4 : g_FQ4;

    int d = threadIdx.x;
    float wp = w[d] * LOG2E;   // only used on q side

#pragma unroll
    for (int r = 0; r < 4; r++) {
        float z = P[(size_t)(row0 + r) * Dx + d];
        float s1, c1;
        __sincosf(OMEGA1 * z, &s1, &c1);
        float s2 = 2.f * s1 * c1;
        float c2 = fmaf(-2.f * s1, s1, 1.f);
        float sm = s1, cm = c1;
#pragma unroll
        for (int h = 0; h < NH; h++) {
            __half2 hv;
            if (which == 0) {
                float sc = c_B[h] * wp;
                hv = __floats2half2_rn(sc * sm, sc * cm);
            } else {
                hv = __floats2half2_rn(cm, sm);
            }
            sbuf[r][h * Dx + d] = *(unsigned*)&hv;
            float ns = fmaf(sm, c2, cm * s2);
            float nc = fmaf(cm, c2, -sm * s2);
            sm = ns; cm = nc;
        }
    }
    __syncthreads();

    const uint4* sb4 = (const uint4*)sbuf;
    for (int i = threadIdx.x; i < 4 * (KP / 8); i += 128) {
        int r = i / (KP / 8), off = i % (KP / 8);
        F4[(size_t)(row0 + r) * (KP / 8) + off] = sb4[i];
    }
}

// ---------------------------------------------------------------------------
// Kernel 3: split-K S = FQ @ FK^T (f16 HMMA, fp32 accum).
// blockIdx.z encodes (batch, K-half): each half computes a partial S over
// KH=1536 K-values into g_S / g_S2 -> 256 blocks, full chip in one wave.
// Block tile 128m x 64n, BK=32, 256 threads (8 warps 4x2), warp tile 32x32.
// ---------------------------------------------------------------------------
__global__ __launch_bounds__(256) void gemm_kernel() {
    __shared__ __half As[2][128][40];   // 20.0 KB
    __shared__ __half Bs[2][64][40];    // 10.0 KB

    int half = blockIdx.z & 1;
    int b = blockIdx.z >> 1;
    int i0 = blockIdx.y * 128;
    int j0 = blockIdx.x * 64;
    const __half* FQ = (const __half*)g_FQ4 + ((size_t)b * Lx + i0) * KP + half * KH;
    const __half* FK = (const __half*)g_FK4 + ((size_t)b * Lx + j0) * KP + half * KH;

    int tid = threadIdx.x;
    int warp = tid >> 5, lane = tid & 31;
    int wr = warp >> 1, wc = warp & 1;

    float acc[2][4][4];
#pragma unroll
    for (int mt = 0; mt < 2; mt++)
#pragma unroll
        for (int nt = 0; nt < 4; nt++)
#pragma unroll
            for (int q = 0; q < 4; q++) acc[mt][nt][q] = 0.f;

    const int NCH = KH / 32;   // 48 chunks

    {
#pragma unroll
        for (int l = 0; l < 2; l++) {
            int idx = tid + 256 * l;
            int row = idx >> 2, seg = idx & 3;
            cp16(saddr(&As[0][row][seg * 8]), FQ + (size_t)row * KP + seg * 8);
        }
        {
            int row = tid >> 2, seg = tid & 3;
            cp16(saddr(&Bs[0][row][seg * 8]), FK + (size_t)row * KP + seg * 8);
        }
        asm volatile("cp.async.commit_group;");
    }

    int buf = 0;
    for (int c = 0; c < NCH; c++) {
        if (c + 1 < NCH) {
            int co = (c + 1) * 32;
#pragma unroll
            for (int l = 0; l < 2; l++) {
                int idx = tid + 256 * l;
                int row = idx >> 2, seg = idx & 3;
                cp16(saddr(&As[buf ^ 1][row][seg * 8]),
                     FQ + (size_t)row * KP + co + seg * 8);
            }
            {
                int row = tid >> 2, seg = tid & 3;
                cp16(saddr(&Bs[buf ^ 1][row][seg * 8]),
                     FK + (size_t)row * KP + co + seg * 8);
            }
            asm volatile("cp.async.commit_group;");
            asm volatile("cp.async.wait_group 1;");
        } else {
            asm volatile("cp.async.wait_group 0;");
        }
        __syncthreads();

#pragma unroll
        for (int ks = 0; ks < 2; ks++) {
            unsigned a[2][4], bb[2][4];
#pragma unroll
            for (int mt = 0; mt < 2; mt++) {
                int row = 32 * wr + 16 * mt + (lane & 7) + 8 * ((lane >> 3) & 1);
                int col = ks * 16 + 8 * (lane >> 4);
                ldsm_x4(a[mt][0], a[mt][1], a[mt][2], a[mt][3],
                        saddr(&As[buf][row][col]));
            }
#pragma unroll
            for (int p = 0; p < 2; p++) {
                int n = 32 * wc + 16 * p + (lane & 7) + 8 * (lane >> 4);
                int col = ks * 16 + 8 * ((lane >> 3) & 1);
                ldsm_x4(bb[p][0], bb[p][1], bb[p][2], bb[p][3],
                        saddr(&Bs[buf][n][col]));
            }
#pragma unroll
            for (int mt = 0; mt < 2; mt++)
#pragma unroll
                for (int nt = 0; nt < 4; nt++)
                    mma16816(acc[mt][nt], a[mt],
                             bb[nt >> 1][2 * (nt & 1)], bb[nt >> 1][2 * (nt & 1) + 1]);
        }
        __syncthreads();
        buf ^= 1;
    }

    float* S = (half ? g_S2 : g_S) + ((size_t)b * Lx + i0) * Lx + j0;
    int g = lane >> 2, tg = lane & 3;
#pragma unroll
    for (int mt = 0; mt < 2; mt++)
#pragma unroll
        for (int nt = 0; nt < 4; nt++) {
            int r = 32 * wr + 16 * mt + g;
            int cc = 32 * wc + 8 * nt + 2 * tg;
            *(float2*)&S[(size_t)r * Lx + cc] =
                make_float2(acc[mt][nt][0], acc[mt][nt][1]);
            *(float2*)&S[(size_t)(r + 8) * Lx + cc] =
                make_float2(acc[mt][nt][2], acc[mt][nt][3]);
        }
}

// ---------------------------------------------------------------------------
// Kernel 4: softmax + out = attn @ x.  4 rows/block (grid 512) for 2x the
// resident warps; S = g_S + g_S2 (split-K combine) on load; cp.async
// double-buffered x tiles as in R9.
// ---------------------------------------------------------------------------
__global__ __launch_bounds__(256) void out_kernel(const float* __restrict__ x,
                                                  float* __restrict__ out) {
    __shared__ float Ps[4][Lx];          // 8 KB
    __shared__ float xs[2][16][Dx];      // 16 KB (two 8KB tiles)
    __shared__ float linv[4];

    int row0 = blockIdx.x * 4;
    int bb = row0 >> 9;
    const float* xb = x + (size_t)bb * Lx * Dx;

    // issue x tiles 0 and 1 (each 16x128 f32 = 512 float4, 2 per thread)
#pragma unroll
    for (int t = 0; t < 2; t++) {
        int idx = threadIdx.x + 256 * t;
        cp16(saddr(&((float*)xs[0])[idx * 4]), xb + idx * 4);
    }
    asm volatile("cp.async.commit_group;");
#pragma unroll
    for (int t = 0; t < 2; t++) {
        int idx = threadIdx.x + 256 * t;
        cp16(saddr(&((float*)xs[1])[idx * 4]), xb + 16 * Dx + idx * 4);
    }
    asm volatile("cp.async.commit_group;");

    // stage S (sum of split-K partials) and softmax — overlaps x tile loads
    const float4* S4a = (const float4*)(g_S + (size_t)row0 * Lx);
    const float4* S4b = (const float4*)(g_S2 + (size_t)row0 * Lx);
    for (int t = threadIdx.x; t < 4 * Lx / 4; t += 256) {
        float4 u = S4a[t], v = S4b[t];
        ((float4*)Ps)[t] = make_float4(u.x + v.x, u.y + v.y, u.z + v.z, u.w + v.w);
    }
    __syncthreads();

    int warp = threadIdx.x >> 5;
    int lane = threadIdx.x & 31;
    if (warp < 4) {
        int r = warp;
        float v[16];
        float m = -1e30f;
#pragma unroll
        for (int c = 0; c < 16; c++) {
            v[c] = Ps[r][lane + c * 32];
            m = fmaxf(m, v[c]);
        }
#pragma unroll
        for (int o = 16; o; o >>= 1) m = fmaxf(m, __shfl_xor_sync(0xffffffffu, m, o));
        float s = 0.f;
#pragma unroll
        for (int c = 0; c < 16; c++) {
            float e = exp2f(v[c] - m);   // scores already include log2e
            s += e;
            Ps[r][lane + c * 32] = e;
        }
#pragma unroll
        for (int o = 16; o; o >>= 1) s += __shfl_xor_sync(0xffffffffu, s, o);
        if (lane == 0) linv[r] = 1.0f / s;
    }

    int d = threadIdx.x & 127;
    int ig = threadIdx.x >> 7;   // 0 -> rows 0,1 ; 1 -> rows 2,3

    float acc[2] = {0.f, 0.f};

    for (int it = 0; it < 32; it++) {
        asm volatile("cp.async.wait_group 1;");
        __syncthreads();   // tile `it` visible; Ps ready (first iter)

        int buf = it & 1;
        int jt = it * 16;
#pragma unroll
        for (int j4 = 0; j4 < 4; j4++) {
            float xv0 = xs[buf][4 * j4 + 0][d];
            float xv1 = xs[buf][4 * j4 + 1][d];
            float xv2 = xs[buf][4 * j4 + 2][d];
            float xv3 = xs[buf][4 * j4 + 3][d];
#pragma unroll
            for (int r = 0; r < 2; r++) {
                float4 p = *(const float4*)&Ps[ig * 2 + r][jt + 4 * j4];
                acc[r] = fmaf(p.x, xv0, acc[r]);
                acc[r] = fmaf(p.y, xv1, acc[r]);
                acc[r] = fmaf(p.z, xv2, acc[r]);
                acc[r] = fmaf(p.w, xv3, acc[r]);
            }
        }
        __syncthreads();   // tile consumed; safe to overwrite buffer

        if (it + 2 < 32) {
#pragma unroll
            for (int t = 0; t < 2; t++) {
                int idx = threadIdx.x + 256 * t;
                cp16(saddr(&((float*)xs[buf])[idx * 4]),
                     xb + (size_t)(it + 2) * 16 * Dx + idx * 4);
            }
        }
        asm volatile("cp.async.commit_group;");   // uniform group count
    }

#pragma unroll
    for (int r = 0; r < 2; r++) {
        int row = row0 + ig * 2 + r;
        out[(size_t)row * Dx + d] = acc[r] * linv[ig * 2 + r];
    }
}

// ---------------------------------------------------------------------------
extern "C" void kernel_launch(void* const* d_in, const int* in_sizes, int n_in,
                              void* d_out, int out_size) {
    const float* x  = (const float*)d_in[0];
    // d_in[1] = mask (bool) — intentionally unused: reference's masked_fill is
    // out-of-place and discarded, so mask has no effect on the output.
    const float* Wq = (const float*)d_in[2];
    const float* bq = (const float*)d_in[3];
    const float* Wk = (const float*)d_in[4];
    const float* bk = (const float*)d_in[5];
    const float* w  = (const float*)d_in[6];
    // d_in[7] = bw — unused: constant score shift cancels in softmax.
    float* out = (float*)d_out;

    dim3 g1(Bx * Lx / 16, 2);
    qk_kernel<<<g1, 256>>>(x, Wq, bq, Wk, bk);

    dim3 gf(Bx * Lx / 4, 2);
    feat_kernel<<<gf, 128>>>(w);

    dim3 gg(Lx / 64, Lx / 128, Bx * 2);
    gemm_kernel<<<gg, 256>>>();

    out_kernel<<<Bx * Lx / 4, 256>>>(x, out);
}

// round 11
// speedup vs baseline: 1.3757x; 1.0906x over previous
#include <cuda_runtime.h>
#include <cuda_fp16.h>

#define Bx 4
#define Lx 512
#define Dx 128
#define NH 12              // harmonics m = 1,3,...,23
#define KP (NH * 2 * Dx)   // 3072 feature dim
#define KH (KP / 2)        // split-K half
#define LOG2E 1.4426950408889634f
#define OMEGA1 0.22439948f // pi/14

// Scratch (static device arrays: allowed; no allocations anywhere)
__device__ float g_Q[Bx * Lx * Dx];               // q projection (pre-tanh)
__device__ float g_K[Bx * Lx * Dx];
__device__ uint4 g_FQ4[(size_t)Bx * Lx * KP / 8]; // f16 features, 16B aligned
__device__ uint4 g_FK4[(size_t)Bx * Lx * KP / 8];
__device__ float g_S[(size_t)Bx * Lx * Lx];       // split-K partial 0
__device__ float g_S2[(size_t)Bx * Lx * Lx];      // split-K partial 1

// Fourier sine coefficients of mirrored tanh: b_m = pi / (7 sinh(m pi^2/28))
__device__ __constant__ float c_B[NH] = {
    1.24737f,     0.354585f,   0.158755f,   0.0766902f,
    0.0376905f,   0.0186002f,  0.00918841f, 0.00454012f,
    0.00224348f,  0.00110862f, 0.000547829f, 0.000270714f
};

__device__ __forceinline__ unsigned saddr(const void* p) {
    return (unsigned)__cvta_generic_to_shared(p);
}
__device__ __forceinline__ void cp16(unsigned dst, const void* src) {
    asm volatile("cp.async.cg.shared.global [%0], [%1], 16;" :: "r"(dst), "l"(src));
}
__device__ __forceinline__ void ldsm_x4(unsigned& r0, unsigned& r1, unsigned& r2,
                                        unsigned& r3, unsigned addr) {
    asm volatile("ldmatrix.sync.aligned.m8n8.x4.shared.b16 {%0,%1,%2,%3}, [%4];"
                 : "=r"(r0), "=r"(r1), "=r"(r2), "=r"(r3) : "r"(addr));
}
__device__ __forceinline__ void mma16816(float* c, const unsigned* a,
                                         unsigned b0, unsigned b1) {
    asm volatile(
        "mma.sync.aligned.m16n8k16.row.col.f32.f16.f16.f32 "
        "{%0,%1,%2,%3}, {%4,%5,%6,%7}, {%8,%9}, {%0,%1,%2,%3};"
        : "+f"(c[0]), "+f"(c[1]), "+f"(c[2]), "+f"(c[3])
        : "r"(a[0]), "r"(a[1]), "r"(a[2]), "r"(a[3]), "r"(b0), "r"(b1));
}
__device__ __forceinline__ float ex2_fast(float v) {
    float y;
    asm("ex2.approx.f32 %0, %1;" : "=f"(y) : "f"(v));
    return y;
}

// ---------------------------------------------------------------------------
// Kernel 1: projections q = x Wq^T + bq, k = x Wk^T + bk.
// Register-prefetch pipeline over 32-d chunks.
// ---------------------------------------------------------------------------
__global__ __launch_bounds__(256) void qk_kernel(
        const float* __restrict__ x,
        const float* __restrict__ Wq, const float* __restrict__ bq,
        const float* __restrict__ Wk, const float* __restrict__ bk) {
    __shared__ float Wsh[32][130];
    __shared__ float xsh[32][20];

    int which = blockIdx.y;
    int row0 = blockIdx.x * 16;
    const float* W = which ? Wk : Wq;
    const float* bias = which ? bk : bq;
    float* outp = which ? g_K : g_Q;

    int tid = threadIdx.x;
    int e0 = 2 * (tid & 63);
    int rg = tid >> 6;

    const float4* W4 = (const float4*)W;
    const float4* x4 = (const float4*)(x + (size_t)row0 * Dx);

    float4 wreg[4];
    float4 xreg;
#pragma unroll
    for (int k = 0; k < 4; k++) {
        int idx = tid + 256 * k;
        wreg[k] = W4[(size_t)(idx >> 3) * 32 + (idx & 7)];
    }
    if (tid < 128) xreg = x4[(size_t)(tid >> 3) * 32 + (tid & 7)];

    float acc[4][2];
#pragma unroll
    for (int r = 0; r < 4; r++) { acc[r][0] = 0.f; acc[r][1] = 0.f; }

    for (int c = 0; c < 4; c++) {
        __syncthreads();
#pragma unroll
        for (int k = 0; k < 4; k++) {
            int idx = tid + 256 * k;
            int e = idx >> 3, j4 = idx & 7;
            Wsh[4 * j4 + 0][e] = wreg[k].x;
            Wsh[4 * j4 + 1][e] = wreg[k].y;
            Wsh[4 * j4 + 2][e] = wreg[k].z;
            Wsh[4 * j4 + 3][e] = wreg[k].w;
        }
        if (tid < 128) {
            int r = tid >> 3, j4 = tid & 7;
            xsh[4 * j4 + 0][r] = xreg.x;
            xsh[4 * j4 + 1][r] = xreg.y;
            xsh[4 * j4 + 2][r] = xreg.z;
            xsh[4 * j4 + 3][r] = xreg.w;
        }
        __syncthreads();

        if (c < 3) {
            int dc4n = (c + 1) * 8;
#pragma unroll
            for (int k = 0; k < 4; k++) {
                int idx = tid + 256 * k;
                wreg[k] = W4[(size_t)(idx >> 3) * 32 + dc4n + (idx & 7)];
            }
            if (tid < 128) xreg = x4[(size_t)(tid >> 3) * 32 + dc4n + (tid & 7)];
        }

#pragma unroll
        for (int d = 0; d < 32; d++) {
            float2 wv = *(const float2*)&Wsh[d][e0];
            float4 xv = *(const float4*)&xsh[d][4 * rg];
            acc[0][0] += wv.x * xv.x;  acc[0][1] += wv.y * xv.x;
            acc[1][0] += wv.x * xv.y;  acc[1][1] += wv.y * xv.y;
            acc[2][0] += wv.x * xv.z;  acc[2][1] += wv.y * xv.z;
            acc[3][0] += wv.x * xv.w;  acc[3][1] += wv.y * xv.w;
        }
    }

    float b0 = bias[e0], b1 = bias[e0 + 1];
#pragma unroll
    for (int r = 0; r < 4; r++) {
        int row = row0 + 4 * rg + r;
        *(float2*)&outp[(size_t)row * Dx + e0] =
            make_float2(acc[r][0] + b0, acc[r][1] + b1);
    }
}

// ---------------------------------------------------------------------------
// Kernel 2: Fourier features.
// Q side: FQ[row][h*256 + 2d]   = b_h * w'_d * sin(w_h q),  +1 = ... * cos
// K side: FK[row][h*256 + 2d]   = cos(w_h k),               +1 = sin(w_h k)
// ---------------------------------------------------------------------------
__global__ __launch_bounds__(128) void feat_kernel(const float* __restrict__ w) {
    __shared__ unsigned sbuf[4][NH * Dx];   // [row][h*128+d] half2 words, 24KB

    int which = blockIdx.y;
    int row0 = blockIdx.x * 4;
    const float* P = which ? g_K : g_Q;
    uint4* F4 = which ? g_FK4 : g_FQ4;

    int d = threadIdx.x;
    float wp = w[d] * LOG2E;   // only used on q side

#pragma unroll
    for (int r = 0; r < 4; r++) {
        float z = P[(size_t)(row0 + r) * Dx + d];
        float s1, c1;
        __sincosf(OMEGA1 * z, &s1, &c1);
        float s2 = 2.f * s1 * c1;
        float c2 = fmaf(-2.f * s1, s1, 1.f);
        float sm = s1, cm = c1;
#pragma unroll
        for (int h = 0; h < NH; h++) {
            __half2 hv;
            if (which == 0) {
                float sc = c_B[h] * wp;
                hv = __floats2half2_rn(sc * sm, sc * cm);
            } else {
                hv = __floats2half2_rn(cm, sm);
            }
            sbuf[r][h * Dx + d] = *(unsigned*)&hv;
            float ns = fmaf(sm, c2, cm * s2);
            float nc = fmaf(cm, c2, -sm * s2);
            sm = ns; cm = nc;
        }
    }
    __syncthreads();

    const uint4* sb4 = (const uint4*)sbuf;
    for (int i = threadIdx.x; i < 4 * (KP / 8); i += 128) {
        int r = i / (KP / 8), off = i % (KP / 8);
        F4[(size_t)(row0 + r) * (KP / 8) + off] = sb4[i];
    }
}

// ---------------------------------------------------------------------------
// Kernel 3: split-K S = FQ @ FK^T (f16 HMMA, fp32 accum).
// blockIdx.z encodes (batch, K-half): 256 blocks, full chip in one wave.
// Block tile 128m x 64n, BK=32, 256 threads (8 warps 4x2), warp tile 32x32.
// ---------------------------------------------------------------------------
__global__ __launch_bounds__(256) void gemm_kernel() {
    __shared__ __half As[2][128][40];   // 20.0 KB
    __shared__ __half Bs[2][64][40];    // 10.0 KB

    int half = blockIdx.z & 1;
    int b = blockIdx.z >> 1;
    int i0 = blockIdx.y * 128;
    int j0 = blockIdx.x * 64;
    const __half* FQ = (const __half*)g_FQ4 + ((size_t)b * Lx + i0) * KP + half * KH;
    const __half* FK = (const __half*)g_FK4 + ((size_t)b * Lx + j0) * KP + half * KH;

    int tid = threadIdx.x;
    int warp = tid >> 5, lane = tid & 31;
    int wr = warp >> 1, wc = warp & 1;

    float acc[2][4][4];
#pragma unroll
    for (int mt = 0; mt < 2; mt++)
#pragma unroll
        for (int nt = 0; nt < 4; nt++)
#pragma unroll
            for (int q = 0; q < 4; q++) acc[mt][nt][q] = 0.f;

    const int NCH = KH / 32;   // 48 chunks

    {
#pragma unroll
        for (int l = 0; l < 2; l++) {
            int idx = tid + 256 * l;
            int row = idx >> 2, seg = idx & 3;
            cp16(saddr(&As[0][row][seg * 8]), FQ + (size_t)row * KP + seg * 8);
        }
        {
            int row = tid >> 2, seg = tid & 3;
            cp16(saddr(&Bs[0][row][seg * 8]), FK + (size_t)row * KP + seg * 8);
        }
        asm volatile("cp.async.commit_group;");
    }

    int buf = 0;
    for (int c = 0; c < NCH; c++) {
        if (c + 1 < NCH) {
            int co = (c + 1) * 32;
#pragma unroll
            for (int l = 0; l < 2; l++) {
                int idx = tid + 256 * l;
                int row = idx >> 2, seg = idx & 3;
                cp16(saddr(&As[buf ^ 1][row][seg * 8]),
                     FQ + (size_t)row * KP + co + seg * 8);
            }
            {
                int row = tid >> 2, seg = tid & 3;
                cp16(saddr(&Bs[buf ^ 1][row][seg * 8]),
                     FK + (size_t)row * KP + co + seg * 8);
            }
            asm volatile("cp.async.commit_group;");
            asm volatile("cp.async.wait_group 1;");
        } else {
            asm volatile("cp.async.wait_group 0;");
        }
        __syncthreads();

#pragma unroll
        for (int ks = 0; ks < 2; ks++) {
            unsigned a[2][4], bb[2][4];
#pragma unroll
            for (int mt = 0; mt < 2; mt++) {
                int row = 32 * wr + 16 * mt + (lane & 7) + 8 * ((lane >> 3) & 1);
                int col = ks * 16 + 8 * (lane >> 4);
                ldsm_x4(a[mt][0], a[mt][1], a[mt][2], a[mt][3],
                        saddr(&As[buf][row][col]));
            }
#pragma unroll
            for (int p = 0; p < 2; p++) {
                int n = 32 * wc + 16 * p + (lane & 7) + 8 * (lane >> 4);
                int col = ks * 16 + 8 * ((lane >> 3) & 1);
                ldsm_x4(bb[p][0], bb[p][1], bb[p][2], bb[p][3],
                        saddr(&Bs[buf][n][col]));
            }
#pragma unroll
            for (int mt = 0; mt < 2; mt++)
#pragma unroll
                for (int nt = 0; nt < 4; nt++)
                    mma16816(acc[mt][nt], a[mt],
                             bb[nt >> 1][2 * (nt & 1)], bb[nt >> 1][2 * (nt & 1) + 1]);
        }
        __syncthreads();
        buf ^= 1;
    }

    float* S = (half ? g_S2 : g_S) + ((size_t)b * Lx + i0) * Lx + j0;
    int g = lane >> 2, tg = lane & 3;
#pragma unroll
    for (int mt = 0; mt < 2; mt++)
#pragma unroll
        for (int nt = 0; nt < 4; nt++) {
            int r = 32 * wr + 16 * mt + g;
            int cc = 32 * wc + 8 * nt + 2 * tg;
            *(float2*)&S[(size_t)r * Lx + cc] =
                make_float2(acc[mt][nt][0], acc[mt][nt][1]);
            *(float2*)&S[(size_t)(r + 8) * Lx + cc] =
                make_float2(acc[mt][nt][2], acc[mt][nt][3]);
        }
}

// ---------------------------------------------------------------------------
// Kernel 4: softmax + out = attn @ x.  8 rows/block (grid 256 — fatter
// blocks amortize the per-block full-x stream; R10's grid-512 regression).
// No max subtraction (|s| <= ~17, exp2 range fp32-safe); exp2 fused into the
// split-K combine pass; cp.async double-buffered x tiles.
// ---------------------------------------------------------------------------
__global__ __launch_bounds__(256) void out_kernel(const float* __restrict__ x,
                                                  float* __restrict__ out) {
    __shared__ float Ps[8][Lx];          // 16 KB (already exponentiated)
    __shared__ float xs[2][16][Dx];      // 16 KB (two 8KB tiles)
    __shared__ float linv[8];

    int row0 = blockIdx.x * 8;
    int bb = row0 >> 9;
    const float* xb = x + (size_t)bb * Lx * Dx;

    // issue x tiles 0 and 1 (each 16x128 f32 = 512 float4, 2 per thread)
#pragma unroll
    for (int t = 0; t < 2; t++) {
        int idx = threadIdx.x + 256 * t;
        cp16(saddr(&((float*)xs[0])[idx * 4]), xb + idx * 4);
    }
    asm volatile("cp.async.commit_group;");
#pragma unroll
    for (int t = 0; t < 2; t++) {
        int idx = threadIdx.x + 256 * t;
        cp16(saddr(&((float*)xs[1])[idx * 4]), xb + 16 * Dx + idx * 4);
    }
    asm volatile("cp.async.commit_group;");

    // combine split-K partials + exp2 in one pass (overlaps x tile loads)
    const float4* S4a = (const float4*)(g_S + (size_t)row0 * Lx);
    const float4* S4b = (const float4*)(g_S2 + (size_t)row0 * Lx);
    for (int t = threadIdx.x; t < 8 * Lx / 4; t += 256) {
        float4 u = S4a[t], v = S4b[t];
        float4 e;
        e.x = ex2_fast(u.x + v.x);
        e.y = ex2_fast(u.y + v.y);
        e.z = ex2_fast(u.z + v.z);
        e.w = ex2_fast(u.w + v.w);
        ((float4*)Ps)[t] = e;
    }
    __syncthreads();

    // row sums (warp w owns row w): 16 loads + 5 shuffles
    int warp = threadIdx.x >> 5;
    int lane = threadIdx.x & 31;
    {
        float s = 0.f;
#pragma unroll
        for (int c = 0; c < 16; c++) s += Ps[warp][lane + c * 32];
#pragma unroll
        for (int o = 16; o; o >>= 1) s += __shfl_xor_sync(0xffffffffu, s, o);
        if (lane == 0) linv[warp] = 1.0f / s;
    }

    int d = threadIdx.x & 127;
    int ig = threadIdx.x >> 7;   // 0 -> rows 0..3, 1 -> rows 4..7

    float acc[4] = {0.f, 0.f, 0.f, 0.f};

    for (int it = 0; it < 32; it++) {
        asm volatile("cp.async.wait_group 1;");
        __syncthreads();   // tile `it` visible; linv/Ps ready (first iter)

        int buf = it & 1;
        int jt = it * 16;
#pragma unroll
        for (int j4 = 0; j4 < 4; j4++) {
            float xv0 = xs[buf][4 * j4 + 0][d];
            float xv1 = xs[buf][4 * j4 + 1][d];
            float xv2 = xs[buf][4 * j4 + 2][d];
            float xv3 = xs[buf][4 * j4 + 3][d];
#pragma unroll
            for (int r = 0; r < 4; r++) {
                float4 p = *(const float4*)&Ps[ig * 4 + r][jt + 4 * j4];
                acc[r] = fmaf(p.x, xv0, acc[r]);
                acc[r] = fmaf(p.y, xv1, acc[r]);
                acc[r] = fmaf(p.z, xv2, acc[r]);
                acc[r] = fmaf(p.w, xv3, acc[r]);
            }
        }
        __syncthreads();   // tile consumed; safe to overwrite buffer

        if (it + 2 < 32) {
#pragma unroll
            for (int t = 0; t < 2; t++) {
                int idx = threadIdx.x + 256 * t;
                cp16(saddr(&((float*)xs[buf])[idx * 4]),
                     xb + (size_t)(it + 2) * 16 * Dx + idx * 4);
            }
        }
        asm volatile("cp.async.commit_group;");   // uniform group count
    }

#pragma unroll
    for (int r = 0; r < 4; r++) {
        int row = row0 + ig * 4 + r;
        out[(size_t)row * Dx + d] = acc[r] * linv[ig * 4 + r];
    }
}

// ---------------------------------------------------------------------------
extern "C" void kernel_launch(void* const* d_in, const int* in_sizes, int n_in,
                              void* d_out, int out_size) {
    const float* x  = (const float*)d_in[0];
    // d_in[1] = mask (bool) — intentionally unused: reference's masked_fill is
    // out-of-place and discarded, so mask has no effect on the output.
    const float* Wq = (const float*)d_in[2];
    const float* bq = (const float*)d_in[3];
    const float* Wk = (const float*)d_in[4];
    const float* bk = (const float*)d_in[5];
    const float* w  = (const float*)d_in[6];
    // d_in[7] = bw — unused: constant score shift cancels in softmax.
    float* out = (float*)d_out;

    dim3 g1(Bx * Lx / 16, 2);
    qk_kernel<<<g1, 256>>>(x, Wq, bq, Wk, bk);

    dim3 gf(Bx * Lx / 4, 2);
    feat_kernel<<<gf, 128>>>(w);

    dim3 gg(Lx / 64, Lx / 128, Bx * 2);
    gemm_kernel<<<gg, 256>>>();

    out_kernel<<<Bx * Lx / 8, 256>>>(x, out);
}